// round 1
// baseline (speedup 1.0000x reference)
#include <cuda_runtime.h>
#include <math.h>

#define BB 64
#define QQ 900
#define GG 100
#define NC 10
#define NC1 11

// -------- device scratch (static: no allocation) --------
__device__ float  g_costT[BB * GG * QQ];   // transposed cost: [b][gt_row_k][q]
__device__ int    g_vlist[BB * GG];        // valid gt indices per batch
__device__ int    g_nvalid[BB];
__device__ int    g_match[BB * QQ];        // per query: matched gt index or -1
__device__ int    g_nmatched;
__device__ double g_cls_num;
__device__ double g_cls_den;
__device__ double g_l1;
__device__ double g_gl;

__global__ void init_kernel() {
    if (threadIdx.x == 0) {
        g_nmatched = 0;
        g_cls_num = 0.0;
        g_cls_den = 0.0;
        g_l1 = 0.0;
        g_gl = 0.0;
    }
}

// one block per batch: compact valid gt indices
__global__ void prep_kernel(const int* __restrict__ gt_classes) {
    int b = blockIdx.x;
    if (threadIdx.x == 0) {
        int n = 0;
        for (int g = 0; g < GG; g++) {
            if (gt_classes[b * GG + g] >= 0) g_vlist[b * GG + n++] = g;
        }
        g_nvalid[b] = n;
    }
}

// cost[b][q][k] -> stored transposed as g_costT[(b*GG + k)*QQ + q]
__global__ void cost_kernel(const float* __restrict__ logits,
                            const float* __restrict__ pboxes,
                            const int*   __restrict__ gtc,
                            const float* __restrict__ gboxes) {
    int b = blockIdx.y;
    int q = blockIdx.x * blockDim.x + threadIdx.x;

    __shared__ float sgx0[GG], sgy0[GG], sgx1[GG], sgy1[GG], sga[GG];
    __shared__ float sgcx[GG], sgcy[GG], sgw[GG], sgh[GG];
    __shared__ int   scls[GG];
    __shared__ int   sn;

    if (threadIdx.x == 0) sn = g_nvalid[b];
    __syncthreads();
    int n = sn;

    for (int k = threadIdx.x; k < n; k += blockDim.x) {
        int gi = g_vlist[b * GG + k];
        const float* gb = gboxes + ((size_t)(b * GG + gi)) * 4;
        float cx = gb[0], cy = gb[1], w = gb[2], h = gb[3];
        float x0 = cx - w * 0.5f, y0 = cy - h * 0.5f;
        float x1 = cx + w * 0.5f, y1 = cy + h * 0.5f;
        sgx0[k] = x0; sgy0[k] = y0; sgx1[k] = x1; sgy1[k] = y1;
        sga[k] = fmaxf(x1 - x0, 0.f) * fmaxf(y1 - y0, 0.f);
        sgcx[k] = cx; sgcy[k] = cy; sgw[k] = w; sgh[k] = h;
        int c = gtc[b * GG + gi];
        scls[k] = (c < 0) ? 0 : (c > NC - 1 ? NC - 1 : c);
    }
    __syncthreads();
    if (q >= QQ) return;

    // softmax over NC1 logits
    const float* lg = logits + ((size_t)(b * QQ + q)) * NC1;
    float e[NC1];
    float mx = lg[0];
#pragma unroll
    for (int c = 1; c < NC1; c++) mx = fmaxf(mx, lg[c]);
    float s = 0.f;
#pragma unroll
    for (int c = 0; c < NC1; c++) { e[c] = expf(lg[c] - mx); s += e[c]; }
    float inv_s = 1.0f / s;

    const float* pb = pboxes + ((size_t)(b * QQ + q)) * 4;
    float pcx = pb[0], pcy = pb[1], pw = pb[2], ph = pb[3];
    float px0 = pcx - pw * 0.5f, py0 = pcy - ph * 0.5f;
    float px1 = pcx + pw * 0.5f, py1 = pcy + ph * 0.5f;
    float pa = fmaxf(px1 - px0, 0.f) * fmaxf(py1 - py0, 0.f);

    float* outc = g_costT + (size_t)b * GG * QQ + q;
    for (int k = 0; k < n; k++) {
        float clsc = -(e[scls[k]] * inv_s);
        float l1 = fabsf(pcx - sgcx[k]) + fabsf(pcy - sgcy[k]) +
                   fabsf(pw - sgw[k]) + fabsf(ph - sgh[k]);
        float gx0 = sgx0[k], gy0 = sgy0[k], gx1 = sgx1[k], gy1 = sgy1[k];
        float ltx = fmaxf(px0, gx0), lty = fmaxf(py0, gy0);
        float rbx = fminf(px1, gx1), rby = fminf(py1, gy1);
        float iw = fmaxf(rbx - ltx, 0.f), ih = fmaxf(rby - lty, 0.f);
        float inter = iw * ih;
        float uni = pa + sga[k] - inter;
        float iou = inter / fmaxf(uni, 1e-6f);
        float ex0 = fminf(px0, gx0), ey0 = fminf(py0, gy0);
        float ex1 = fmaxf(px1, gx1), ey1 = fmaxf(py1, gy1);
        float ew = fmaxf(ex1 - ex0, 0.f), eh = fmaxf(ey1 - ey0, 0.f);
        float enc = ew * eh;
        float giou = iou - (enc - uni) / fmaxf(enc, 1e-6f);
        outc[(size_t)k * QQ] = 2.0f * clsc + 5.0f * l1 - 2.0f * giou;
    }
}

// Jonker-Volgenant shortest augmenting path; one block per batch.
// Rows = valid gts (n <= 100), cols = queries (m = 900). Doubles to match
// reference float64 arithmetic.
__global__ void __launch_bounds__(256) jv_kernel() {
    const int b = blockIdx.x;
    const int tid = threadIdx.x;
    const int m = QQ;
    const int n = g_nvalid[b];

    __shared__ double sv[QQ + 1];
    __shared__ double sminv[QQ + 1];
    __shared__ double su[GG + 2];
    __shared__ int    sway[QQ + 1];
    __shared__ int    sp[QQ + 1];
    __shared__ unsigned char sused[QQ + 1];
    __shared__ double rval[256];
    __shared__ int    ridx[256];
    __shared__ int    sj0;

    for (int j = tid; j <= m; j += 256) { sv[j] = 0.0; sp[j] = 0; }
    for (int i = tid; i <= n; i += 256) su[i] = 0.0;
    __syncthreads();

    for (int i = 1; i <= n; i++) {
        for (int j = tid; j <= m; j += 256) {
            sminv[j] = 1e300;
            sway[j] = 0;
            sused[j] = 0;
        }
        if (tid == 0) { sp[0] = i; sj0 = 0; }
        __syncthreads();

        while (true) {
            int j0 = sj0;
            if (tid == 0) sused[j0] = 1;
            __syncthreads();

            int i0 = sp[j0];
            double ui0 = su[i0];
            const float* Crow = g_costT + ((size_t)(b * GG + (i0 - 1))) * QQ;

            double lmin = 1e300;
            int lj = m + 1;
            for (int j = tid + 1; j <= m; j += 256) {
                if (!sused[j]) {
                    double cur = (double)Crow[j - 1] - ui0 - sv[j];
                    if (cur < sminv[j]) { sminv[j] = cur; sway[j] = j0; }
                    double mv = sminv[j];
                    if (mv < lmin) { lmin = mv; lj = j; }
                }
            }
            rval[tid] = lmin;
            ridx[tid] = lj;
            __syncthreads();
#pragma unroll
            for (int s = 128; s > 0; s >>= 1) {
                if (tid < s) {
                    double ov = rval[tid + s];
                    int oi = ridx[tid + s];
                    if (ov < rval[tid] || (ov == rval[tid] && oi < ridx[tid])) {
                        rval[tid] = ov;
                        ridx[tid] = oi;
                    }
                }
                __syncthreads();
            }
            int j1 = ridx[0];
            double delta = rval[0];
            __syncthreads();

            for (int j = tid; j <= m; j += 256) {
                if (sused[j]) {
                    su[sp[j]] += delta;   // distinct sp[j] among used cols -> no race
                    sv[j] -= delta;
                } else {
                    sminv[j] -= delta;
                }
            }
            if (tid == 0) sj0 = j1;
            __syncthreads();
            if (sp[j1] == 0) break;
        }

        if (tid == 0) {
            int j0 = sj0;
            while (j0 != 0) {
                int jn = sway[j0];
                sp[j0] = sp[jn];
                j0 = jn;
            }
        }
        __syncthreads();
    }

    for (int j = tid + 1; j <= m; j += 256) {
        int r = sp[j];
        g_match[b * QQ + (j - 1)] = (r > 0) ? g_vlist[b * GG + (r - 1)] : -1;
    }
    if (tid == 0) atomicAdd(&g_nmatched, n);
}

__global__ void loss_kernel(const float* __restrict__ logits,
                            const float* __restrict__ pboxes,
                            const int*   __restrict__ gtc,
                            const float* __restrict__ gboxes) {
    int idx = blockIdx.x * blockDim.x + threadIdx.x;
    double nllw = 0.0, wsum = 0.0, l1acc = 0.0, glacc = 0.0;

    if (idx < BB * QQ) {
        int b = idx / QQ;
        const float* lg = logits + (size_t)idx * NC1;
        float mx = lg[0];
#pragma unroll
        for (int c = 1; c < NC1; c++) mx = fmaxf(mx, lg[c]);
        float s = 0.f;
#pragma unroll
        for (int c = 0; c < NC1; c++) s += expf(lg[c] - mx);
        float logZ = mx + logf(s);

        int mg = g_match[idx];
        int t = (mg >= 0) ? gtc[b * GG + mg] : NC;
        float logp = lg[t] - logZ;
        float wt = (t == NC) ? 0.1f : 1.0f;
        nllw = (double)(wt * (-logp));
        wsum = (double)wt;

        if (mg >= 0) {
            const float* pb = pboxes + (size_t)idx * 4;
            const float* gb = gboxes + ((size_t)(b * GG + mg)) * 4;
            float pcx = pb[0], pcy = pb[1], pw = pb[2], ph = pb[3];
            float gcx = gb[0], gcy = gb[1], gw = gb[2], gh = gb[3];
            l1acc = (double)(fabsf(pcx - gcx) + fabsf(pcy - gcy) +
                             fabsf(pw - gw) + fabsf(ph - gh));
            float px0 = pcx - pw * 0.5f, py0 = pcy - ph * 0.5f;
            float px1 = pcx + pw * 0.5f, py1 = pcy + ph * 0.5f;
            float gx0 = gcx - gw * 0.5f, gy0 = gcy - gh * 0.5f;
            float gx1 = gcx + gw * 0.5f, gy1 = gcy + gh * 0.5f;
            float pa = fmaxf(px1 - px0, 0.f) * fmaxf(py1 - py0, 0.f);
            float ga = fmaxf(gx1 - gx0, 0.f) * fmaxf(gy1 - gy0, 0.f);
            float ltx = fmaxf(px0, gx0), lty = fmaxf(py0, gy0);
            float rbx = fminf(px1, gx1), rby = fminf(py1, gy1);
            float iw = fmaxf(rbx - ltx, 0.f), ih = fmaxf(rby - lty, 0.f);
            float inter = iw * ih;
            float uni = pa + ga - inter;
            float iou = inter / fmaxf(uni, 1e-6f);
            float ex0 = fminf(px0, gx0), ey0 = fminf(py0, gy0);
            float ex1 = fmaxf(px1, gx1), ey1 = fmaxf(py1, gy1);
            float ew = fmaxf(ex1 - ex0, 0.f), eh = fmaxf(ey1 - ey0, 0.f);
            float enc = ew * eh;
            float giou = iou - (enc - uni) / fmaxf(enc, 1e-6f);
            glacc = (double)(1.0f - giou);
        }
    }

    __shared__ double s1[256], s2[256], s3[256], s4[256];
    int tid = threadIdx.x;
    s1[tid] = nllw; s2[tid] = wsum; s3[tid] = l1acc; s4[tid] = glacc;
    __syncthreads();
#pragma unroll
    for (int s = 128; s > 0; s >>= 1) {
        if (tid < s) {
            s1[tid] += s1[tid + s];
            s2[tid] += s2[tid + s];
            s3[tid] += s3[tid + s];
            s4[tid] += s4[tid + s];
        }
        __syncthreads();
    }
    if (tid == 0) {
        atomicAdd(&g_cls_num, s1[0]);
        atomicAdd(&g_cls_den, s2[0]);
        atomicAdd(&g_l1, s3[0]);
        atomicAdd(&g_gl, s4[0]);
    }
}

__global__ void finalize_kernel(float* __restrict__ out) {
    if (threadIdx.x == 0) {
        int nm = g_nmatched;
        if (nm < 1) nm = 1;
        double nmd = (double)nm;
        double cls = g_cls_num / g_cls_den;
        out[0] = (float)(2.0 * cls + 5.0 * g_l1 / nmd + 2.0 * g_gl / nmd);
    }
}

extern "C" void kernel_launch(void* const* d_in, const int* in_sizes, int n_in,
                              void* d_out, int out_size) {
    const float* pred_logits = (const float*)d_in[0];
    const float* pred_boxes  = (const float*)d_in[1];
    const int*   gt_classes  = (const int*)d_in[2];
    const float* gt_boxes    = (const float*)d_in[3];
    float* out = (float*)d_out;

    init_kernel<<<1, 32>>>();
    prep_kernel<<<BB, 32>>>(gt_classes);

    dim3 cgrid((QQ + 127) / 128, BB);
    cost_kernel<<<cgrid, 128>>>(pred_logits, pred_boxes, gt_classes, gt_boxes);

    jv_kernel<<<BB, 256>>>();

    int total = BB * QQ;
    loss_kernel<<<(total + 255) / 256, 256>>>(pred_logits, pred_boxes,
                                              gt_classes, gt_boxes);
    finalize_kernel<<<1, 32>>>(out);
}